// round 2
// baseline (speedup 1.0000x reference)
#include <cuda_runtime.h>
#include <cstdint>

#define DEVINL __device__ __forceinline__

constexpr int BB = 256;            // batch
constexpr int II = 512;            // input dim
constexpr int RR = 1024;           // hidden dim
constexpr int UU = 11;             // unroll length
constexpr int NSTEP = 10;          // steps that actually matter (step 10 is dead)
constexpr int OUTLD = UU * RR;     // 11264, row stride of output
constexpr int PRELD = NSTEP * 4 * RR;  // 40960, row stride of PreX

constexpr int BM = 64;             // CTA m-tile
constexpr int KC = 16;             // k-chunk
constexpr int ALD = KC + 4;        // padded smem row (20) -> conflict-free frag loads

// Scratch (allocation-free rule: __device__ globals)
__device__ __align__(16) float g_preX[(size_t)BB * PRELD];   // 41.9 MB
__device__ __align__(16) float g_h0buf[2][BB * RR];          // ping-pong h0
__device__ __align__(16) float g_c0[BB * RR];
__device__ __align__(16) float g_c1[BB * RR];

DEVINL void cp16(float* s, const float* g) {
    uint32_t sa = (uint32_t)__cvta_generic_to_shared(s);
    asm volatile("cp.async.cg.shared.global [%0], [%1], 16;" :: "r"(sa), "l"(g));
}
DEVINL void cp_commit() { asm volatile("cp.async.commit_group;"); }
DEVINL void cp_wait0()  { asm volatile("cp.async.wait_group 0;"); }
DEVINL void cp_wait1()  { asm volatile("cp.async.wait_group 1;"); }

DEVINL uint32_t f2tf(float f) {
    uint32_t u; asm("cvt.rna.tf32.f32 %0, %1;" : "=r"(u) : "f"(f)); return u;
}

DEVINL void mma8(float* d, const uint32_t* a, const uint32_t* b) {
    asm volatile(
        "mma.sync.aligned.m16n8k8.row.col.f32.tf32.tf32.f32 "
        "{%0,%1,%2,%3}, {%4,%5,%6,%7}, {%8,%9}, {%0,%1,%2,%3};"
        : "+f"(d[0]), "+f"(d[1]), "+f"(d[2]), "+f"(d[3])
        : "r"(a[0]), "r"(a[1]), "r"(a[2]), "r"(a[3]), "r"(b[0]), "r"(b[1]));
}

DEVINL float sigm(float x) { return 1.0f / (1.0f + expf(-x)); }

// Unified TN GEMM: C[m, ncols] = sum_p A_p[m,:] @ W_p[rows,:]^T, where the CTA's
// 128 output columns are 4 groups of 32 with W-row stride `gstride`.
//   EPI 0: precompute  -> store acc + e0[col] + e1[col] into hout (PreX)
//   EPI 1: layer0 cell -> base = PreX (e0), state c0, write h0_next
//   EPI 2: layer1 cell -> base = bi1+bh1 (e0,e1), state c1, write h1 into d_out
template<int EPI, int NPAIRS>
__global__ __launch_bounds__(256, 1)
void lstm_gemm(const float* __restrict__ A0, int lda0,
               const float* __restrict__ W0,
               const float* __restrict__ A1, int lda1,
               const float* __restrict__ W1,
               int K, int gstride, int nbmul,
               const float* __restrict__ e0,
               const float* __restrict__ e1,
               float* __restrict__ cst,
               float* __restrict__ hout, int ldh)
{
    __shared__ __align__(16) float As[2][BM][ALD];
    __shared__ __align__(16) float Bs[2][128][ALD];

    const int tid  = threadIdx.x;
    const int warp = tid >> 5, lane = tid & 31;
    const int wm = warp >> 2, wn = warp & 3;       // 2 x 4 warp grid over 64x128 tile
    const int gid = lane >> 2, tig = lane & 3;     // mma fragment coords
    const int m0 = blockIdx.x * BM;
    const int nbase = blockIdx.y * nbmul;

    const int ar  = tid >> 2;              // A row this thread loads (64 rows)
    const int seg = (tid & 3) << 2;        // 4-float segment within k-chunk
    const int br0 = ar, br1 = ar + 64;     // B (weight) rows this thread loads
    const int grow0 = nbase + (br0 >> 5) * gstride + (br0 & 31);
    const int grow1 = nbase + (br1 >> 5) * gstride + (br1 & 31);

    float acc[2][4][4];
    #pragma unroll
    for (int a = 0; a < 2; a++)
        #pragma unroll
        for (int b = 0; b < 4; b++)
            #pragma unroll
            for (int c = 0; c < 4; c++) acc[a][b][c] = 0.0f;

    #pragma unroll
    for (int p = 0; p < NPAIRS; p++) {
        const float* A   = (p == 0) ? A0 : A1;
        const int    lda = (p == 0) ? lda0 : lda1;
        const float* W   = (p == 0) ? W0 : W1;
        const int nk = K / KC;

        const float* Ag  = A + (size_t)(m0 + ar) * lda + seg;
        const float* Wg0 = W + (size_t)grow0 * K + seg;
        const float* Wg1 = W + (size_t)grow1 * K + seg;

        // prologue: chunk 0 -> buf 0
        cp16(&As[0][ar][seg],  Ag);
        cp16(&Bs[0][br0][seg], Wg0);
        cp16(&Bs[0][br1][seg], Wg1);
        cp_commit();

        for (int t = 0; t < nk; t++) {
            const int buf = t & 1;
            if (t + 1 < nk) {
                const int kc = (t + 1) * KC;
                cp16(&As[buf ^ 1][ar][seg],  Ag + kc);
                cp16(&Bs[buf ^ 1][br0][seg], Wg0 + kc);
                cp16(&Bs[buf ^ 1][br1][seg], Wg1 + kc);
                cp_commit();
                cp_wait1();
            } else {
                cp_wait0();
            }
            __syncthreads();

            #pragma unroll
            for (int ks = 0; ks < KC / 8; ks++) {
                const int ko = ks * 8;
                uint32_t ua[2][4];
                #pragma unroll
                for (int mi = 0; mi < 2; mi++) {
                    const float* ab = &As[buf][wm * 32 + mi * 16 + gid][ko + tig];
                    ua[mi][0] = f2tf(ab[0]);
                    ua[mi][1] = f2tf(ab[8 * ALD]);
                    ua[mi][2] = f2tf(ab[4]);
                    ua[mi][3] = f2tf(ab[8 * ALD + 4]);
                }
                uint32_t ub[4][2];
                #pragma unroll
                for (int g = 0; g < 4; g++) {
                    const float* bb = &Bs[buf][g * 32 + wn * 8 + gid][ko + tig];
                    ub[g][0] = f2tf(bb[0]);
                    ub[g][1] = f2tf(bb[4]);
                }
                #pragma unroll
                for (int mi = 0; mi < 2; mi++)
                    #pragma unroll
                    for (int g = 0; g < 4; g++)
                        mma8(acc[mi][g], ua[mi], ub[g]);
            }
            __syncthreads();
        }
    }

    // ---- epilogue ----
    #pragma unroll
    for (int mi = 0; mi < 2; mi++) {
        #pragma unroll
        for (int half = 0; half < 2; half++) {
            const int row = wm * 32 + mi * 16 + gid + half * 8;
            const int b = m0 + row;
            #pragma unroll
            for (int cc = 0; cc < 2; cc++) {
                const int reg = half * 2 + cc;
                if constexpr (EPI == 0) {
                    #pragma unroll
                    for (int g = 0; g < 4; g++) {
                        const int col = nbase + g * gstride + wn * 8 + 2 * tig + cc;
                        hout[(size_t)b * ldh + col] = acc[mi][g][reg] + e0[col] + e1[col];
                    }
                } else {
                    const int r = nbase + wn * 8 + 2 * tig + cc;
                    float pre[4];
                    #pragma unroll
                    for (int g = 0; g < 4; g++) {
                        float base;
                        if constexpr (EPI == 1)
                            base = e0[(size_t)b * PRELD + g * RR + r];  // e0 = g_preX + u*4096
                        else
                            base = e0[g * RR + r] + e1[g * RR + r];     // bi1[u] + bh1[u]
                        pre[g] = acc[mi][g][reg] + base;
                    }
                    const float cprev = cst[b * RR + r];
                    const float iv = sigm(pre[0]);
                    const float fv = sigm(pre[1]);
                    const float ov = sigm(pre[2]);
                    const float gv = tanhf(pre[3]);
                    const float cnew = fv * cprev + iv * gv;
                    const float hnew = ov * tanhf(cnew);
                    cst[b * RR + r] = cnew;
                    hout[(size_t)b * ldh + r] = hnew;
                }
            }
        }
    }
}

__global__ void init_states(const float* __restrict__ st, float* __restrict__ out) {
    int idx = blockIdx.x * blockDim.x + threadIdx.x;
    if (idx >= BB * RR) return;
    int b = idx >> 10, r = idx & (RR - 1);
    const float* s = st + (size_t)b * (4 * RR);
    g_h0buf[0][idx] = s[r];                        // h0
    g_c0[idx]       = s[RR + r];                   // c0
    out[(size_t)b * OUTLD + r] = s[2 * RR + r];    // h1 -> output col 0 (and state)
    g_c1[idx]       = s[3 * RR + r];               // c1
}

extern "C" void kernel_launch(void* const* d_in, const int* in_sizes, int n_in,
                              void* d_out, int out_size)
{
    const float* x   = (const float*)d_in[0];
    const float* ini = (const float*)d_in[1];
    const float* Wi0 = (const float*)d_in[2];
    const float* bi0 = (const float*)d_in[3];
    const float* Wh0 = (const float*)d_in[4];
    const float* bh0 = (const float*)d_in[5];
    const float* Wi1 = (const float*)d_in[6];
    const float* bi1 = (const float*)d_in[7];
    const float* Wh1 = (const float*)d_in[8];
    const float* bh1 = (const float*)d_in[9];
    float* out = (float*)d_out;

    float *preX, *h0buf, *c0, *c1;
    cudaGetSymbolAddress((void**)&preX,  g_preX);
    cudaGetSymbolAddress((void**)&h0buf, g_h0buf);
    cudaGetSymbolAddress((void**)&c0,    g_c0);
    cudaGetSymbolAddress((void**)&c1,    g_c1);
    float* h0a = h0buf;
    float* h0b = h0buf + (size_t)BB * RR;

    init_states<<<(BB * RR) / 256, 256>>>(ini, out);

    // PreX[b, u*4096 + n] = x @ Wi0[0:10].T + bi0 + bh0   (Wi0 rows for u<10 are
    // the first 40960 rows of the flattened (11*4096, 512) matrix; biases likewise)
    lstm_gemm<0, 1><<<dim3(BB / BM, PRELD / 128), 256>>>(
        x, II, Wi0, nullptr, 0, nullptr,
        II, /*gstride=*/32, /*nbmul=*/128,
        bi0, bh0, nullptr, preX, PRELD);

    for (int u = 0; u < NSTEP; u++) {
        float* h0cur = (u & 1) ? h0b : h0a;
        float* h0nxt = (u & 1) ? h0a : h0b;

        // layer 0: pre0 = PreX[u] + h0 @ Wh0[u].T  -> cell -> h0nxt, c0
        lstm_gemm<1, 1><<<dim3(BB / BM, RR / 32), 256>>>(
            h0cur, RR, Wh0 + (size_t)u * 4 * RR * RR,
            nullptr, 0, nullptr,
            RR, /*gstride=*/RR, /*nbmul=*/32,
            preX + (size_t)u * 4 * RR, nullptr,
            c0, h0nxt, RR);

        // layer 1: pre1 = h0nxt @ Wi1[u].T + h1 @ Wh1[u].T + bi1[u] + bh1[u]
        //          -> cell -> h1 written directly into output column (u+1)
        lstm_gemm<2, 2><<<dim3(BB / BM, RR / 32), 256>>>(
            h0nxt, RR, Wi1 + (size_t)u * 4 * RR * RR,
            out + (size_t)u * RR, OUTLD, Wh1 + (size_t)u * 4 * RR * RR,
            RR, /*gstride=*/RR, /*nbmul=*/32,
            bi1 + (size_t)u * 4 * RR, bh1 + (size_t)u * 4 * RR,
            c1, out + (size_t)(u + 1) * RR, OUTLD);
    }
}

// round 3
// speedup vs baseline: 1.3857x; 1.3857x over previous
#include <cuda_runtime.h>
#include <cstdint>

#define DEVINL __device__ __forceinline__

constexpr int BB = 256;            // batch
constexpr int II = 512;            // input dim
constexpr int RR = 1024;           // hidden dim
constexpr int UU = 11;             // unroll length
constexpr int NSTEP = 10;          // steps that matter (step 10 is dead)
constexpr int OUTLD = UU * RR;     // output row stride
constexpr int PRELD = NSTEP * 4 * RR;  // PreX row stride

constexpr int BM = 64;             // CTA m-tile
constexpr int KC = 16;             // k-chunk
constexpr int ALD = KC + 4;        // padded smem row -> conflict-free frag loads

// Scratch (allocation-free rule: __device__ globals)
__device__ __align__(16) float g_preX[(size_t)BB * PRELD];
__device__ __align__(16) float g_h0buf[2][BB * RR];
__device__ __align__(16) float g_c0[BB * RR];
__device__ __align__(16) float g_c1[BB * RR];

struct Smem {
    float As[2][BM][ALD];
    float Bs[2][128][ALD];
};

DEVINL void cp16(float* s, const float* g) {
    uint32_t sa = (uint32_t)__cvta_generic_to_shared(s);
    asm volatile("cp.async.cg.shared.global [%0], [%1], 16;" :: "r"(sa), "l"(g));
}
DEVINL void cp_commit() { asm volatile("cp.async.commit_group;"); }
DEVINL void cp_wait0()  { asm volatile("cp.async.wait_group 0;"); }
DEVINL void cp_wait1()  { asm volatile("cp.async.wait_group 1;"); }

DEVINL uint32_t f2tf(float f) {
    uint32_t u; asm("cvt.rna.tf32.f32 %0, %1;" : "=r"(u) : "f"(f)); return u;
}

DEVINL void mma8(float* d, const uint32_t* a, const uint32_t* b) {
    asm volatile(
        "mma.sync.aligned.m16n8k8.row.col.f32.tf32.tf32.f32 "
        "{%0,%1,%2,%3}, {%4,%5,%6,%7}, {%8,%9}, {%0,%1,%2,%3};"
        : "+f"(d[0]), "+f"(d[1]), "+f"(d[2]), "+f"(d[3])
        : "r"(a[0]), "r"(a[1]), "r"(a[2]), "r"(a[3]), "r"(b[0]), "r"(b[1]));
}

DEVINL float sigm(float x) { return 1.0f / (1.0f + expf(-x)); }

// Unified TN GEMM body: C[64, 128] tile = sum_p A_p @ W_p^T; the 128 output
// columns are 4 groups of 32 with W-row stride `gstride` (the 4 LSTM gates).
//   EPI 0: precompute -> acc + e0[col] + e1[col] into hout (PreX)
//   EPI 1: layer0 cell -> base = PreX (e0), state c0, write h0_next
//   EPI 2: layer1 cell -> base = bi1+bh1, state c1, write h1
template<int EPI, int NPAIRS>
DEVINL void gemm_body(Smem& sm, int m0, int nbase,
                      const float* __restrict__ A0, int lda0,
                      const float* __restrict__ W0,
                      const float* __restrict__ A1, int lda1,
                      const float* __restrict__ W1,
                      int K, int gstride,
                      const float* __restrict__ e0,
                      const float* __restrict__ e1,
                      float* __restrict__ cst,
                      float* __restrict__ hout, int ldh)
{
    const int tid  = threadIdx.x;
    const int warp = tid >> 5, lane = tid & 31;
    const int wm = warp >> 2, wn = warp & 3;       // 2 x 4 warps over 64x128
    const int gid = lane >> 2, tig = lane & 3;

    const int ar  = tid >> 2;
    const int seg = (tid & 3) << 2;
    const int br0 = ar, br1 = ar + 64;
    const int grow0 = nbase + (br0 >> 5) * gstride + (br0 & 31);
    const int grow1 = nbase + (br1 >> 5) * gstride + (br1 & 31);

    float acc[2][4][4];
    #pragma unroll
    for (int a = 0; a < 2; a++)
        #pragma unroll
        for (int b = 0; b < 4; b++)
            #pragma unroll
            for (int c = 0; c < 4; c++) acc[a][b][c] = 0.0f;

    #pragma unroll
    for (int p = 0; p < NPAIRS; p++) {
        const float* A   = (p == 0) ? A0 : A1;
        const int    lda = (p == 0) ? lda0 : lda1;
        const float* W   = (p == 0) ? W0 : W1;
        const int nk = K / KC;

        const float* Ag  = A + (size_t)(m0 + ar) * lda + seg;
        const float* Wg0 = W + (size_t)grow0 * K + seg;
        const float* Wg1 = W + (size_t)grow1 * K + seg;

        cp16(&sm.As[0][ar][seg],  Ag);
        cp16(&sm.Bs[0][br0][seg], Wg0);
        cp16(&sm.Bs[0][br1][seg], Wg1);
        cp_commit();

        for (int t = 0; t < nk; t++) {
            const int buf = t & 1;
            if (t + 1 < nk) {
                const int kc = (t + 1) * KC;
                cp16(&sm.As[buf ^ 1][ar][seg],  Ag + kc);
                cp16(&sm.Bs[buf ^ 1][br0][seg], Wg0 + kc);
                cp16(&sm.Bs[buf ^ 1][br1][seg], Wg1 + kc);
                cp_commit();
                cp_wait1();
            } else {
                cp_wait0();
            }
            __syncthreads();

            #pragma unroll
            for (int ks = 0; ks < KC / 8; ks++) {
                const int ko = ks * 8;
                uint32_t ua[2][4];
                #pragma unroll
                for (int mi = 0; mi < 2; mi++) {
                    const float* ab = &sm.As[buf][wm * 32 + mi * 16 + gid][ko + tig];
                    ua[mi][0] = f2tf(ab[0]);
                    ua[mi][1] = f2tf(ab[8 * ALD]);
                    ua[mi][2] = f2tf(ab[4]);
                    ua[mi][3] = f2tf(ab[8 * ALD + 4]);
                }
                uint32_t ub[4][2];
                #pragma unroll
                for (int g = 0; g < 4; g++) {
                    const float* bb = &sm.Bs[buf][g * 32 + wn * 8 + gid][ko + tig];
                    ub[g][0] = f2tf(bb[0]);
                    ub[g][1] = f2tf(bb[4]);
                }
                #pragma unroll
                for (int mi = 0; mi < 2; mi++)
                    #pragma unroll
                    for (int g = 0; g < 4; g++)
                        mma8(acc[mi][g], ua[mi], ub[g]);
            }
            __syncthreads();
        }
    }

    // ---- epilogue ----
    #pragma unroll
    for (int mi = 0; mi < 2; mi++) {
        #pragma unroll
        for (int half = 0; half < 2; half++) {
            const int row = wm * 32 + mi * 16 + gid + half * 8;
            const int b = m0 + row;
            #pragma unroll
            for (int cc = 0; cc < 2; cc++) {
                const int reg = half * 2 + cc;
                if constexpr (EPI == 0) {
                    #pragma unroll
                    for (int g = 0; g < 4; g++) {
                        const int col = nbase + g * gstride + wn * 8 + 2 * tig + cc;
                        hout[(size_t)b * ldh + col] = acc[mi][g][reg] + e0[col] + e1[col];
                    }
                } else {
                    const int r = nbase + wn * 8 + 2 * tig + cc;
                    float pre[4];
                    #pragma unroll
                    for (int g = 0; g < 4; g++) {
                        float base;
                        if constexpr (EPI == 1)
                            base = e0[(size_t)b * PRELD + g * RR + r];
                        else
                            base = e0[g * RR + r] + e1[g * RR + r];
                        pre[g] = acc[mi][g][reg] + base;
                    }
                    const float cprev = cst[b * RR + r];
                    const float iv = sigm(pre[0]);
                    const float fv = sigm(pre[1]);
                    const float ov = sigm(pre[2]);
                    const float gv = tanhf(pre[3]);
                    const float cnew = fv * cprev + iv * gv;
                    const float hnew = ov * tanhf(cnew);
                    cst[b * RR + r] = cnew;
                    hout[(size_t)b * ldh + r] = hnew;
                }
            }
        }
    }
}

// ---- kernels ----

__global__ __launch_bounds__(256, 2)
void k_pre(const float* __restrict__ x, const float* __restrict__ Wi0,
           const float* __restrict__ bi0, const float* __restrict__ bh0,
           float* __restrict__ preX)
{
    __shared__ Smem sm;
    gemm_body<0, 1>(sm, blockIdx.x * BM, blockIdx.y * 128,
                    x, II, Wi0, nullptr, 0, nullptr,
                    II, 32, bi0, bh0, nullptr, preX, PRELD);
}

__global__ __launch_bounds__(256, 2)
void k_l0(const float* __restrict__ h0cur, const float* __restrict__ Wh0u,
          const float* __restrict__ preXu, float* __restrict__ c0,
          float* __restrict__ h0nxt)
{
    __shared__ Smem sm;
    gemm_body<1, 1>(sm, blockIdx.x * BM, blockIdx.y * 32,
                    h0cur, RR, Wh0u, nullptr, 0, nullptr,
                    RR, RR, preXu, nullptr, c0, h0nxt, RR);
}

__global__ __launch_bounds__(256, 2)
void k_l1(const float* __restrict__ h0cur, const float* __restrict__ Wi1u,
          const float* __restrict__ h1in, const float* __restrict__ Wh1u,
          const float* __restrict__ bi1u, const float* __restrict__ bh1u,
          float* __restrict__ c1, float* __restrict__ h1out)
{
    __shared__ Smem sm;
    gemm_body<2, 2>(sm, blockIdx.x * BM, blockIdx.y * 32,
                    h0cur, RR, Wi1u, h1in, OUTLD, Wh1u,
                    RR, RR, bi1u, bh1u, c1, h1out, OUTLD);
}

// Combined step: L1(u) [y 0..31] and L0(u+1) [y 32..63] are independent —
// both consume h0 produced by L0(u). One launch, 256 CTAs, one wave @2/SM.
__global__ __launch_bounds__(256, 2)
void k_step(const float* __restrict__ h0cur, float* __restrict__ h0nxt,
            const float* __restrict__ Wi1u, const float* __restrict__ Wh1u,
            const float* __restrict__ bi1u, const float* __restrict__ bh1u,
            const float* __restrict__ h1in, float* __restrict__ h1out,
            const float* __restrict__ Wh0n, const float* __restrict__ preXn,
            float* __restrict__ c0, float* __restrict__ c1)
{
    __shared__ Smem sm;
    const int m0 = blockIdx.x * BM;
    if (blockIdx.y < 32) {
        gemm_body<2, 2>(sm, m0, blockIdx.y * 32,
                        h0cur, RR, Wi1u, h1in, OUTLD, Wh1u,
                        RR, RR, bi1u, bh1u, c1, h1out, OUTLD);
    } else {
        gemm_body<1, 1>(sm, m0, (blockIdx.y - 32) * 32,
                        h0cur, RR, Wh0n, nullptr, 0, nullptr,
                        RR, RR, preXn, nullptr, c0, h0nxt, RR);
    }
}

__global__ void init_states(const float* __restrict__ st, float* __restrict__ out) {
    int idx = blockIdx.x * blockDim.x + threadIdx.x;
    if (idx >= BB * RR) return;
    int b = idx >> 10, r = idx & (RR - 1);
    const float* s = st + (size_t)b * (4 * RR);
    g_h0buf[0][idx] = s[r];                        // h0
    g_c0[idx]       = s[RR + r];                   // c0
    out[(size_t)b * OUTLD + r] = s[2 * RR + r];    // h1 -> output col 0 (state)
    g_c1[idx]       = s[3 * RR + r];               // c1
}

extern "C" void kernel_launch(void* const* d_in, const int* in_sizes, int n_in,
                              void* d_out, int out_size)
{
    const float* x   = (const float*)d_in[0];
    const float* ini = (const float*)d_in[1];
    const float* Wi0 = (const float*)d_in[2];
    const float* bi0 = (const float*)d_in[3];
    const float* Wh0 = (const float*)d_in[4];
    const float* bh0 = (const float*)d_in[5];
    const float* Wi1 = (const float*)d_in[6];
    const float* bi1 = (const float*)d_in[7];
    const float* Wh1 = (const float*)d_in[8];
    const float* bh1 = (const float*)d_in[9];
    float* out = (float*)d_out;

    float *preX, *h0buf, *c0, *c1;
    cudaGetSymbolAddress((void**)&preX,  g_preX);
    cudaGetSymbolAddress((void**)&h0buf, g_h0buf);
    cudaGetSymbolAddress((void**)&c0,    g_c0);
    cudaGetSymbolAddress((void**)&c1,    g_c1);

    // h0 ping-pong: L0(k) reads buf[k&1], writes buf[(k+1)&1]
    auto h0b = [&](int i) { return h0buf + (size_t)i * BB * RR; };

    init_states<<<(BB * RR) / 256, 256>>>(ini, out);

    // PreX = x @ Wi0[0:10].T + bi0 + bh0  (all 10 live steps at once)
    k_pre<<<dim3(BB / BM, PRELD / 128), 256>>>(x, Wi0, bi0, bh0, preX);

    // L0(0): h0 buf0 -> buf1
    k_l0<<<dim3(BB / BM, RR / 32), 256>>>(h0b(0), Wh0, preX, c0, h0b(1));

    // C(u) = L1(u) + L0(u+1), u = 0..8
    for (int u = 0; u < NSTEP - 1; u++) {
        const size_t wo = (size_t)u * 4 * RR * RR;
        const size_t wn_ = (size_t)(u + 1) * 4 * RR * RR;
        const size_t bo = (size_t)u * 4 * RR;
        k_step<<<dim3(BB / BM, 64), 256>>>(
            h0b((u + 1) & 1), h0b(u & 1),
            Wi1 + wo, Wh1 + wo, bi1 + bo, bh1 + bo,
            out + (size_t)u * RR, out + (size_t)(u + 1) * RR,
            Wh0 + wn_, preX + (size_t)(u + 1) * 4 * RR,
            c0, c1);
    }

    // final L1(9)
    {
        const int u = NSTEP - 1;
        const size_t wo = (size_t)u * 4 * RR * RR;
        const size_t bo = (size_t)u * 4 * RR;
        k_l1<<<dim3(BB / BM, RR / 32), 256>>>(
            h0b((u + 1) & 1), Wi1 + wo,
            out + (size_t)u * RR, Wh1 + wo,
            bi1 + bo, bh1 + bo,
            c1, out + (size_t)(u + 1) * RR);
    }
}